// round 6
// baseline (speedup 1.0000x reference)
#include <cuda_runtime.h>
#include <cstdint>

// Conv2D: x[4096,4096] fp32, w[15,15], valid -> out[4082,4082] + bias.
//
// Round 6 = Round 5 (packed f32x2 FMA) with the weight-staging bug fixed:
// NT=128 threads but 225 weights -> must stage with a strided loop, not
// `if (tid < 225)` (left s_w2[128..224] uninitialized -> rel_err 0.88).
//
//  - Output columns paired: acc = (out[j], out[j+1]) as packed f32x2 (FFMA2).
//  - Weights pre-packed (w,w) in smem -> one broadcast LDS.64 per tap.
//  - Tile 128(x) x 48(y), 128 threads (8x x 16y), thread: 16 cols x 3 rows.
//  - Row-reuse over input rows t=0..16 (ky = t - r), t-loop rolled (I$-safe).
//  - cp.async staging.

#define HI 4096
#define WI 4096
#define KH 15
#define KW 15
#define OH (HI - KH + 1)   // 4082
#define OW (WI - KW + 1)   // 4082

#define TOX 128
#define TOY 48
#define RX  16
#define RY  3
#define NT  128

#define IN_ROWS (TOY + KH - 1)   // 62
#define PITCH   144              // floats per smem row, 16B-aligned

typedef unsigned long long u64;

__device__ __forceinline__ u64 pack2(float x, float y) {
    u64 r; asm("mov.b64 %0, {%1, %2};" : "=l"(r) : "f"(x), "f"(y)); return r;
}
__device__ __forceinline__ u64 fma2(u64 a, u64 b, u64 c) {
    u64 d; asm("fma.rn.f32x2 %0, %1, %2, %3;" : "=l"(d) : "l"(a), "l"(b), "l"(c));
    return d;
}
__device__ __forceinline__ u64 add2(u64 a, u64 b) {
    u64 d; asm("add.rn.f32x2 %0, %1, %2;" : "=l"(d) : "l"(a), "l"(b)); return d;
}

__global__ __launch_bounds__(NT, 3)
void conv2d_v6_kernel(const float* __restrict__ x,
                      const float* __restrict__ w,
                      const float* __restrict__ bias,
                      float* __restrict__ out)
{
    __shared__ float s_in[IN_ROWS][PITCH];       // 35.7 KB
    __shared__ float2 s_w2[KH * KW];             // (w,w) pairs, 1.8 KB

    const int tid = threadIdx.x;
    const int ox0 = blockIdx.x * TOX;
    const int oy0 = blockIdx.y * TOY;

    // ---- Stage weights as (w,w) pairs (strided: NT=128 < 225!) ----
    #pragma unroll
    for (int i = tid; i < KH * KW; i += NT) {
        const float wv = w[i];
        s_w2[i] = make_float2(wv, wv);
    }

    // ---- Stage input tile via cp.async (62 rows x 36 float4) ----
    // ox0 multiple of 128, WI%4==0 -> each float4 fully in- or out-of-range.
    #pragma unroll 2
    for (int i = tid; i < IN_ROWS * 36; i += NT) {
        const int r  = i / 36;
        const int c  = (i - r * 36) * 4;
        const int gy = oy0 + r;
        const int gx = ox0 + c;
        const uint32_t sa = (uint32_t)__cvta_generic_to_shared(&s_in[r][c]);
        if (gy < HI && gx < WI) {
            const float* gp = &x[(long)gy * WI + gx];
            asm volatile("cp.async.cg.shared.global [%0], [%1], 16;"
                         :: "r"(sa), "l"(gp) : "memory");
        } else {
            *reinterpret_cast<float4*>(&s_in[r][c]) = make_float4(0.f, 0.f, 0.f, 0.f);
        }
    }
    asm volatile("cp.async.commit_group;" ::: "memory");
    asm volatile("cp.async.wait_group 0;" ::: "memory");
    __syncthreads();

    const int tx = tid & 7;    // 8 column groups x RX=16 -> 128 cols
    const int ty = tid >> 3;   // 16 row strips x RY=3    -> 48 rows

    u64 acc[RY][RX / 2];
    #pragma unroll
    for (int r = 0; r < RY; ++r)
        #pragma unroll
        for (int p = 0; p < RX / 2; ++p) acc[r][p] = 0ull;

    // ---- Main loop over input rows (rolled; I$-safe body) ----
    #pragma unroll 1
    for (int t = 0; t < RY + KH - 1; ++t) {      // 17 rows per strip
        // Load 32 input floats via 8 conflict-free LDS.128.
        float a[32];
        const float* rp = &s_in[ty * RY + t][tx * RX];
        #pragma unroll
        for (int q = 0; q < 8; ++q) {
            const float4 v = *reinterpret_cast<const float4*>(rp + 4 * q);
            a[4 * q + 0] = v.x; a[4 * q + 1] = v.y;
            a[4 * q + 2] = v.z; a[4 * q + 3] = v.w;
        }
        // Aligned pairs A[i]=(a[2i],a[2i+1]); shifted S[i]=(a[2i+1],a[2i+2]).
        u64 A[15], S[15];
        #pragma unroll
        for (int i = 0; i < 15; ++i) {
            A[i] = pack2(a[2 * i], a[2 * i + 1]);
            S[i] = pack2(a[2 * i + 1], a[2 * i + 2]);
        }

        #pragma unroll
        for (int r = 0; r < RY; ++r) {
            if ((unsigned)(t - r) < (unsigned)KH) {   // ky in range (uniform)
                const float2* wrow = &s_w2[(t - r) * KW];
                #pragma unroll
                for (int kx = 0; kx < KW; ++kx) {
                    const u64 wp = *reinterpret_cast<const u64*>(&wrow[kx]);
                    #pragma unroll
                    for (int p = 0; p < RX / 2; ++p) {
                        const int idx = kx + 2 * p;
                        const u64 in = (kx & 1) ? S[(idx - 1) >> 1] : A[idx >> 1];
                        acc[r][p] = fma2(in, wp, acc[r][p]);
                    }
                }
            }
        }
    }

    // ---- Epilogue: bias + packed 8B stores ----
    const float b = __ldg(&bias[0]);
    const u64 bb = pack2(b, b);
    #pragma unroll
    for (int r = 0; r < RY; ++r) {
        const int oy = oy0 + ty * RY + r;
        if (oy >= OH) continue;
        float* orow = &out[(long)oy * OW];
        #pragma unroll
        for (int p = 0; p < RX / 2; ++p) {
            const int ox = ox0 + tx * RX + 2 * p;
            if (ox + 1 < OW) {   // OW even, ox even -> pair never straddles
                *reinterpret_cast<u64*>(&orow[ox]) = add2(acc[r][p], bb);
            }
        }
    }
}

extern "C" void kernel_launch(void* const* d_in, const int* in_sizes, int n_in,
                              void* d_out, int out_size)
{
    const float* x    = (const float*)d_in[0];
    const float* w    = (const float*)d_in[1];
    const float* bias = (const float*)d_in[2];
    float* out        = (float*)d_out;

    dim3 grid((OW + TOX - 1) / TOX,   // 32
              (OH + TOY - 1) / TOY);  // 86
    conv2d_v6_kernel<<<grid, NT>>>(x, w, bias, out);
}

// round 7
// speedup vs baseline: 1.2407x; 1.2407x over previous
#include <cuda_runtime.h>
#include <cstdint>

// Conv2D: x[4096,4096] fp32, w[15,15], valid -> out[4082,4082] + bias.
//
// Round 7: scalar FFMA, outer-ky loop, tuned for occupancy.
//  - FFMA2 (round 6) measured rt=2 -> no FLOP gain; back to scalar FFMA
//    which sustains ~1/cyc/SMSP.
//  - Outer ky (15 rolled iters): weight row = 15 regs reloaded per ky
//    (broadcast LDS). No 45-reg window -> regs ~80 -> 6 CTAs/SM
//    (24 warps/SM vs round 4's 16) to fix issue=69.6%.
//  - Tile 128(x) x 24(y), NT=128: tx 16 x RX 8, ty 8 x RY 3.
//  - Per ky: 15 w-LDS + 3 x (6 LDS.128 + 120 FFMA). 88.5% FFMA mix.
//  - cp.async staging; float2 stores (out rows only 8B-aligned).

#define HI 4096
#define WI 4096
#define KH 15
#define KW 15
#define OH (HI - KH + 1)   // 4082
#define OW (WI - KW + 1)   // 4082

#define TOX 128
#define TOY 24
#define RX  8
#define RY  3
#define NT  128

#define IN_ROWS (TOY + KH - 1)   // 38
#define PITCH   144              // floats per smem row

__global__ __launch_bounds__(NT, 6)
void conv2d_v7_kernel(const float* __restrict__ x,
                      const float* __restrict__ w,
                      const float* __restrict__ bias,
                      float* __restrict__ out)
{
    __shared__ float s_in[IN_ROWS][PITCH];   // 21.9 KB
    __shared__ float s_w[KH * KW];

    const int tid = threadIdx.x;
    const int ox0 = blockIdx.x * TOX;
    const int oy0 = blockIdx.y * TOY;

    // ---- Stage weights (strided: NT=128 < 225) ----
    #pragma unroll
    for (int i = tid; i < KH * KW; i += NT) s_w[i] = w[i];

    // ---- Stage input tile via cp.async (38 rows x 36 float4) ----
    // ox0 multiple of 128, WI%4==0 -> each float4 fully in- or out-of-range.
    #pragma unroll 2
    for (int i = tid; i < IN_ROWS * 36; i += NT) {
        const int r  = i / 36;
        const int c  = (i - r * 36) * 4;
        const int gy = oy0 + r;
        const int gx = ox0 + c;
        const uint32_t sa = (uint32_t)__cvta_generic_to_shared(&s_in[r][c]);
        if (gy < HI && gx < WI) {
            const float* gp = &x[(long)gy * WI + gx];
            asm volatile("cp.async.cg.shared.global [%0], [%1], 16;"
                         :: "r"(sa), "l"(gp) : "memory");
        } else {
            *reinterpret_cast<float4*>(&s_in[r][c]) = make_float4(0.f, 0.f, 0.f, 0.f);
        }
    }
    asm volatile("cp.async.commit_group;" ::: "memory");
    asm volatile("cp.async.wait_group 0;" ::: "memory");
    __syncthreads();

    const int tx = tid & 15;   // column group (8 wide)
    const int ty = tid >> 4;   // row strip (3 rows)

    float acc[RY][RX];
    #pragma unroll
    for (int r = 0; r < RY; ++r)
        #pragma unroll
        for (int j = 0; j < RX; ++j) acc[r][j] = 0.f;

    // ---- Outer loop over kernel rows (rolled; body ~6.5KB, L0-resident) ----
    #pragma unroll 1
    for (int ky = 0; ky < KH; ++ky) {
        // Weight row ky -> 15 regs (uniform-address broadcast LDS).
        float wr[KW];
        #pragma unroll
        for (int kx = 0; kx < KW; ++kx) wr[kx] = s_w[ky * KW + kx];

        #pragma unroll
        for (int r = 0; r < RY; ++r) {
            // 24 input floats (need 22) via 6 LDS.128.
            float a[24];
            const float* rp = &s_in[ty * RY + r + ky][tx * RX];
            #pragma unroll
            for (int q = 0; q < 6; ++q) {
                const float4 v = *reinterpret_cast<const float4*>(rp + 4 * q);
                a[4 * q + 0] = v.x; a[4 * q + 1] = v.y;
                a[4 * q + 2] = v.z; a[4 * q + 3] = v.w;
            }
            #pragma unroll
            for (int kx = 0; kx < KW; ++kx)
                #pragma unroll
                for (int j = 0; j < RX; ++j)
                    acc[r][j] = fmaf(wr[kx], a[kx + j], acc[r][j]);
        }
    }

    // ---- Epilogue: bias + float2 stores (8B-aligned: OW even, ox even) ----
    const float b = __ldg(&bias[0]);
    #pragma unroll
    for (int r = 0; r < RY; ++r) {
        const int oy = oy0 + ty * RY + r;
        if (oy >= OH) continue;
        float* orow = &out[(long)oy * OW];
        #pragma unroll
        for (int p = 0; p < 4; ++p) {
            const int ox = ox0 + tx * RX + 2 * p;
            if (ox + 1 < OW) {   // pair never straddles (OW even, ox even)
                float2 v = make_float2(acc[r][2 * p] + b, acc[r][2 * p + 1] + b);
                *reinterpret_cast<float2*>(&orow[ox]) = v;
            }
        }
    }
}

extern "C" void kernel_launch(void* const* d_in, const int* in_sizes, int n_in,
                              void* d_out, int out_size)
{
    const float* x    = (const float*)d_in[0];
    const float* w    = (const float*)d_in[1];
    const float* bias = (const float*)d_in[2];
    float* out        = (float*)d_out;

    dim3 grid((OW + TOX - 1) / TOX,   // 32
              (OH + TOY - 1) / TOY);  // 171
    conv2d_v7_kernel<<<grid, NT>>>(x, w, bias, out);
}

// round 8
// speedup vs baseline: 1.4728x; 1.1871x over previous
#include <cuda_runtime.h>
#include <cstdint>

// Conv2D: x[4096,4096] fp32, w[15,15], valid -> out[4082,4082] + bias.
//
// Round 8: R4 row-reuse dataflow + register diet -> 5 CTAs/SM.
//  - RY=3 row-reuse (crossbar 47%, validated R4) with 45-reg weight window.
//  - Two-stage input consumption per row (kx 0-8 on a[0..15], then kx 9-14
//    on a[9..21]) cuts peak live input regs 24 -> 16.
//  - __launch_bounds__(128,5): 20 warps/SM (vs R4's 16) to fix issue=69.6%.
//  - cp.async staging; weight-row LDS hoisted to iteration top.
//  - float2 stores (out rows only 8B-aligned); strided weight staging.

#define HI 4096
#define WI 4096
#define KH 15
#define KW 15
#define OH (HI - KH + 1)   // 4082
#define OW (WI - KW + 1)   // 4082

#define TOX 128
#define TOY 24
#define RX  8
#define RY  3
#define NT  128

#define IN_ROWS (TOY + KH - 1)   // 38
#define PITCH   144              // floats per smem row

__global__ __launch_bounds__(NT, 5)
void conv2d_v8_kernel(const float* __restrict__ x,
                      const float* __restrict__ w,
                      const float* __restrict__ bias,
                      float* __restrict__ out)
{
    __shared__ float s_in[IN_ROWS][PITCH];   // 21.9 KB
    __shared__ float s_w[KH * KW];

    const int tid = threadIdx.x;
    const int ox0 = blockIdx.x * TOX;
    const int oy0 = blockIdx.y * TOY;

    // ---- Stage weights (strided: NT=128 < 225) ----
    #pragma unroll
    for (int i = tid; i < KH * KW; i += NT) s_w[i] = w[i];

    // ---- Stage input tile via cp.async (38 rows x 36 float4) ----
    // ox0 multiple of 128, WI%4==0 -> each float4 fully in- or out-of-range.
    #pragma unroll 2
    for (int i = tid; i < IN_ROWS * 36; i += NT) {
        const int r  = i / 36;
        const int c  = (i - r * 36) * 4;
        const int gy = oy0 + r;
        const int gx = ox0 + c;
        const uint32_t sa = (uint32_t)__cvta_generic_to_shared(&s_in[r][c]);
        if (gy < HI && gx < WI) {
            const float* gp = &x[(long)gy * WI + gx];
            asm volatile("cp.async.cg.shared.global [%0], [%1], 16;"
                         :: "r"(sa), "l"(gp) : "memory");
        } else {
            *reinterpret_cast<float4*>(&s_in[r][c]) = make_float4(0.f, 0.f, 0.f, 0.f);
        }
    }
    asm volatile("cp.async.commit_group;" ::: "memory");
    asm volatile("cp.async.wait_group 0;" ::: "memory");
    __syncthreads();

    const int tx = tid & 15;   // column group (8 wide)
    const int ty = tid >> 4;   // row strip (3 rows)

    float acc[RY][RX];
    #pragma unroll
    for (int r = 0; r < RY; ++r)
        #pragma unroll
        for (int j = 0; j < RX; ++j) acc[r][j] = 0.f;

    float wk[3][KW];           // rotating weight-row window, slot = ky % 3

    // t = 0..16, in 6 groups of 3 so slot (t-r)%3 == (c-r)%3 is compile-time.
    #pragma unroll 1
    for (int u = 0; u < 6; ++u) {
        #pragma unroll
        for (int c = 0; c < 3; ++c) {
            const int t = 3 * u + c;
            if (t < RY + KH - 1) {                 // skip t == 17
                if (t < KH) {                      // weight row t -> slot c
                    #pragma unroll
                    for (int kx = 0; kx < KW; ++kx)
                        wk[c][kx] = s_w[t * KW + kx];
                }

                #pragma unroll
                for (int r = 0; r < RY; ++r) {
                    if ((unsigned)(t - r) < (unsigned)KH) {     // ky in range
                        const int slot = ((c - r) % 3 + 3) % 3; // compile-time
                        const float* rp = &s_in[ty * RY + t][tx * RX];

                        // Stage 1: a[0..15], taps kx = 0..8.
                        float a[16];
                        #pragma unroll
                        for (int q = 0; q < 4; ++q) {
                            const float4 v = *reinterpret_cast<const float4*>(rp + 4 * q);
                            a[4 * q + 0] = v.x; a[4 * q + 1] = v.y;
                            a[4 * q + 2] = v.z; a[4 * q + 3] = v.w;
                        }
                        #pragma unroll
                        for (int kx = 0; kx <= 8; ++kx) {
                            const float wv = wk[slot][kx];
                            #pragma unroll
                            for (int j = 0; j < RX; ++j)
                                acc[r][j] = fmaf(wv, a[kx + j], acc[r][j]);
                        }

                        // Stage 2: a[16..23], taps kx = 9..14 (need a[9..21]).
                        float a2[8];
                        #pragma unroll
                        for (int q = 0; q < 2; ++q) {
                            const float4 v = *reinterpret_cast<const float4*>(rp + 16 + 4 * q);
                            a2[4 * q + 0] = v.x; a2[4 * q + 1] = v.y;
                            a2[4 * q + 2] = v.z; a2[4 * q + 3] = v.w;
                        }
                        #pragma unroll
                        for (int kx = 9; kx < KW; ++kx) {
                            const float wv = wk[slot][kx];
                            #pragma unroll
                            for (int j = 0; j < RX; ++j) {
                                const int idx = kx + j;   // 9..21
                                const float av = (idx < 16) ? a[idx] : a2[idx - 16];
                                acc[r][j] = fmaf(wv, av, acc[r][j]);
                            }
                        }
                    }
                }
            }
        }
    }

    // ---- Epilogue: bias + float2 stores (8B-aligned: OW even, ox even) ----
    const float b = __ldg(&bias[0]);
    #pragma unroll
    for (int r = 0; r < RY; ++r) {
        const int oy = oy0 + ty * RY + r;
        if (oy >= OH) continue;
        float* orow = &out[(long)oy * OW];
        #pragma unroll
        for (int p = 0; p < 4; ++p) {
            const int ox = ox0 + tx * RX + 2 * p;
            if (ox + 1 < OW) {   // pair never straddles (OW even, ox even)
                float2 v = make_float2(acc[r][2 * p] + b, acc[r][2 * p + 1] + b);
                *reinterpret_cast<float2*>(&orow[ox]) = v;
            }
        }
    }
}

extern "C" void kernel_launch(void* const* d_in, const int* in_sizes, int n_in,
                              void* d_out, int out_size)
{
    const float* x    = (const float*)d_in[0];
    const float* w    = (const float*)d_in[1];
    const float* bias = (const float*)d_in[2];
    float* out        = (float*)d_out;

    dim3 grid((OW + TOX - 1) / TOX,   // 32
              (OH + TOY - 1) / TOY);  // 171
    conv2d_v8_kernel<<<grid, NT>>>(x, w, bias, out);
}

// round 9
// speedup vs baseline: 1.5409x; 1.0463x over previous
#include <cuda_runtime.h>
#include <cstdint>

// Conv2D: x[4096,4096] fp32, w[15,15], valid -> out[4082,4082] + bias.
//
// Round 9 = Round 8 occupancy + Round 4 crossbar economy.
//  - Input row loaded ONCE per t (hoisted out of the r loop), reused by all
//    RY=3 accumulator rows: 102 LDS.128/thread (R8 did 306 -> L1=88%).
//  - Register diet kept via two stages ACROSS the r loop:
//      stage 1: a[0..15] (4 LDS.128) -> all r, taps kx=0..8
//      stage 2: a[16..23] (2 LDS.128) -> all r, taps kx=9..14
//    Peak live ~95 regs -> still 5 CTAs/SM (20 warps/SM).
//  - 45-reg rotating weight window, statically indexed via unroll-by-3.
//  - cp.async staging; float2 stores (out rows only 8B-aligned).

#define HI 4096
#define WI 4096
#define KH 15
#define KW 15
#define OH (HI - KH + 1)   // 4082
#define OW (WI - KW + 1)   // 4082

#define TOX 128
#define TOY 24
#define RX  8
#define RY  3
#define NT  128

#define IN_ROWS (TOY + KH - 1)   // 38
#define PITCH   144              // floats per smem row

__global__ __launch_bounds__(NT, 5)
void conv2d_v9_kernel(const float* __restrict__ x,
                      const float* __restrict__ w,
                      const float* __restrict__ bias,
                      float* __restrict__ out)
{
    __shared__ float s_in[IN_ROWS][PITCH];   // 21.9 KB
    __shared__ float s_w[KH * KW];

    const int tid = threadIdx.x;
    const int ox0 = blockIdx.x * TOX;
    const int oy0 = blockIdx.y * TOY;

    // ---- Stage weights (strided: NT=128 < 225) ----
    #pragma unroll
    for (int i = tid; i < KH * KW; i += NT) s_w[i] = w[i];

    // ---- Stage input tile via cp.async (38 rows x 36 float4) ----
    // ox0 multiple of 128, WI%4==0 -> each float4 fully in- or out-of-range.
    #pragma unroll 2
    for (int i = tid; i < IN_ROWS * 36; i += NT) {
        const int r  = i / 36;
        const int c  = (i - r * 36) * 4;
        const int gy = oy0 + r;
        const int gx = ox0 + c;
        const uint32_t sa = (uint32_t)__cvta_generic_to_shared(&s_in[r][c]);
        if (gy < HI && gx < WI) {
            const float* gp = &x[(long)gy * WI + gx];
            asm volatile("cp.async.cg.shared.global [%0], [%1], 16;"
                         :: "r"(sa), "l"(gp) : "memory");
        } else {
            *reinterpret_cast<float4*>(&s_in[r][c]) = make_float4(0.f, 0.f, 0.f, 0.f);
        }
    }
    asm volatile("cp.async.commit_group;" ::: "memory");
    asm volatile("cp.async.wait_group 0;" ::: "memory");
    __syncthreads();

    const int tx = tid & 15;   // column group (8 wide)
    const int ty = tid >> 4;   // row strip (3 rows)

    float acc[RY][RX];
    #pragma unroll
    for (int r = 0; r < RY; ++r)
        #pragma unroll
        for (int j = 0; j < RX; ++j) acc[r][j] = 0.f;

    float wk[3][KW];           // rotating weight-row window, slot = ky % 3

    // t = 0..16, in 6 groups of 3 so slot (t-r)%3 == (c-r)%3 is compile-time.
    #pragma unroll 1
    for (int u = 0; u < 6; ++u) {
        #pragma unroll
        for (int c = 0; c < 3; ++c) {
            const int t = 3 * u + c;
            if (t < RY + KH - 1) {                 // skip t == 17
                if (t < KH) {                      // weight row t -> slot c
                    #pragma unroll
                    for (int kx = 0; kx < KW; ++kx)
                        wk[c][kx] = s_w[t * KW + kx];
                }

                const float* rp = &s_in[ty * RY + t][tx * RX];

                // ---- Stage 1: a[0..15] feeds taps kx=0..8 for ALL rows ----
                float a[16];
                #pragma unroll
                for (int q = 0; q < 4; ++q) {
                    const float4 v = *reinterpret_cast<const float4*>(rp + 4 * q);
                    a[4 * q + 0] = v.x; a[4 * q + 1] = v.y;
                    a[4 * q + 2] = v.z; a[4 * q + 3] = v.w;
                }
                #pragma unroll
                for (int r = 0; r < RY; ++r) {
                    if ((unsigned)(t - r) < (unsigned)KH) {     // ky in range
                        const int slot = ((c - r) % 3 + 3) % 3; // compile-time
                        #pragma unroll
                        for (int kx = 0; kx <= 8; ++kx) {
                            const float wv = wk[slot][kx];
                            #pragma unroll
                            for (int j = 0; j < RX; ++j)
                                acc[r][j] = fmaf(wv, a[kx + j], acc[r][j]);
                        }
                    }
                }

                // ---- Stage 2: a2 = a[16..23] feeds taps kx=9..14 ----
                float a2[8];
                #pragma unroll
                for (int q = 0; q < 2; ++q) {
                    const float4 v = *reinterpret_cast<const float4*>(rp + 16 + 4 * q);
                    a2[4 * q + 0] = v.x; a2[4 * q + 1] = v.y;
                    a2[4 * q + 2] = v.z; a2[4 * q + 3] = v.w;
                }
                #pragma unroll
                for (int r = 0; r < RY; ++r) {
                    if ((unsigned)(t - r) < (unsigned)KH) {
                        const int slot = ((c - r) % 3 + 3) % 3;
                        #pragma unroll
                        for (int kx = 9; kx < KW; ++kx) {
                            const float wv = wk[slot][kx];
                            #pragma unroll
                            for (int j = 0; j < RX; ++j) {
                                const int idx = kx + j;   // 9..21
                                const float av = (idx < 16) ? a[idx] : a2[idx - 16];
                                acc[r][j] = fmaf(wv, av, acc[r][j]);
                            }
                        }
                    }
                }
            }
        }
    }

    // ---- Epilogue: bias + float2 stores (8B-aligned: OW even, ox even) ----
    const float b = __ldg(&bias[0]);
    #pragma unroll
    for (int r = 0; r < RY; ++r) {
        const int oy = oy0 + ty * RY + r;
        if (oy >= OH) continue;
        float* orow = &out[(long)oy * OW];
        #pragma unroll
        for (int p = 0; p < 4; ++p) {
            const int ox = ox0 + tx * RX + 2 * p;
            if (ox + 1 < OW) {   // pair never straddles (OW even, ox even)
                float2 v = make_float2(acc[r][2 * p] + b, acc[r][2 * p + 1] + b);
                *reinterpret_cast<float2*>(&orow[ox]) = v;
            }
        }
    }
}

extern "C" void kernel_launch(void* const* d_in, const int* in_sizes, int n_in,
                              void* d_out, int out_size)
{
    const float* x    = (const float*)d_in[0];
    const float* w    = (const float*)d_in[1];
    const float* bias = (const float*)d_in[2];
    float* out        = (float*)d_out;

    dim3 grid((OW + TOX - 1) / TOX,   // 32
              (OH + TOY - 1) / TOY);  // 171
    conv2d_v9_kernel<<<grid, NT>>>(x, w, bias, out);
}